// round 3
// baseline (speedup 1.0000x reference)
#include <cuda_runtime.h>
#include <cuda_bf16.h>

// loss = sum_{pos} softplus(-p)/n_pos + sum_{neg} softplus(p)/n_neg
// over 8192x8192 f32 + i32. Streaming reduction, HBM-bound.
// R3 (= R2 retry after infra failure): 4-deep load batching (MLP_p1=8)
// + fused last-block final reduction.

#define NBLOCKS  1184        // 148 SMs * 8 CTAs
#define NTHREADS 256
#define N_TOTAL  67108864    // 8192*8192
#define N_VEC4   16777216    // N_TOTAL / 4
#define UNROLL   4

__device__ float g_pos[NBLOCKS];
__device__ float g_neg[NBLOCKS];
__device__ int   g_cnt[NBLOCKS];
__device__ int   g_ticket;   // zero-init at module load; last block resets it

// softplus(x)  = log1p(e^{-|x|}) + max(x, 0)
// softplus(-x) = log1p(e^{-|x|}) + max(-x, 0)
// -> one EX2 + one LG2 per element regardless of label.
__device__ __forceinline__ void lane_accum(float x, int y,
                                           float& pos, float& neg, int& cnt) {
    float ax     = fabsf(x);
    float common = __logf(1.0f + __expf(-ax));
    bool  ispos  = (y != 0);
    float relu   = fmaxf(ispos ? -x : x, 0.0f);
    float v      = common + relu;
    pos += ispos ? v : 0.0f;
    neg += ispos ? 0.0f : v;
    cnt += ispos ? 1 : 0;
}

__global__ __launch_bounds__(NTHREADS)
void micro_loss_kernel(const float4* __restrict__ pred,
                       const int4*  __restrict__ ty,
                       float* __restrict__ out) {
    float pos = 0.0f, neg = 0.0f;
    int   cnt = 0;

    const int stride = gridDim.x * blockDim.x;
    int i = blockIdx.x * blockDim.x + threadIdx.x;

    // Batched main loop: front-issue 8 independent LDG.128, then compute.
    for (; i + (UNROLL - 1) * stride < N_VEC4; i += UNROLL * stride) {
        float4 p[UNROLL];
        int4   y[UNROLL];
        #pragma unroll
        for (int k = 0; k < UNROLL; k++) {
            p[k] = __ldcs(pred + i + k * stride);
            y[k] = __ldcs(ty   + i + k * stride);
        }
        #pragma unroll
        for (int k = 0; k < UNROLL; k++) {
            lane_accum(p[k].x, y[k].x, pos, neg, cnt);
            lane_accum(p[k].y, y[k].y, pos, neg, cnt);
            lane_accum(p[k].z, y[k].z, pos, neg, cnt);
            lane_accum(p[k].w, y[k].w, pos, neg, cnt);
        }
    }
    // Remainder (<= UNROLL-1 iterations per thread)
    for (; i < N_VEC4; i += stride) {
        float4 p = __ldcs(pred + i);
        int4   y = __ldcs(ty + i);
        lane_accum(p.x, y.x, pos, neg, cnt);
        lane_accum(p.y, y.y, pos, neg, cnt);
        lane_accum(p.z, y.z, pos, neg, cnt);
        lane_accum(p.w, y.w, pos, neg, cnt);
    }

    // Block reduction (fixed tree -> deterministic)
    #pragma unroll
    for (int o = 16; o > 0; o >>= 1) {
        pos += __shfl_down_sync(0xFFFFFFFFu, pos, o);
        neg += __shfl_down_sync(0xFFFFFFFFu, neg, o);
        cnt += __shfl_down_sync(0xFFFFFFFFu, cnt, o);
    }
    __shared__ float sp[NTHREADS / 32];
    __shared__ float sn[NTHREADS / 32];
    __shared__ int   sc[NTHREADS / 32];
    __shared__ bool  s_last;
    int wid = threadIdx.x >> 5;
    int lid = threadIdx.x & 31;
    if (lid == 0) { sp[wid] = pos; sn[wid] = neg; sc[wid] = cnt; }
    __syncthreads();

    if (threadIdx.x == 0) {
        constexpr int NW = NTHREADS / 32;
        float bp = 0.0f, bn = 0.0f; int bc = 0;
        #pragma unroll
        for (int w = 0; w < NW; w++) { bp += sp[w]; bn += sn[w]; bc += sc[w]; }
        g_pos[blockIdx.x] = bp;
        g_neg[blockIdx.x] = bn;
        g_cnt[blockIdx.x] = bc;
        __threadfence();
        int ticket = atomicAdd(&g_ticket, 1);
        s_last = (ticket == NBLOCKS - 1);
    }
    __syncthreads();

    // Last-arriving block performs the final reduction (fixed order -> deterministic).
    if (s_last) {
        __threadfence();  // acquire: all blocks' partials visible
        float fp = 0.0f, fn = 0.0f; int fc = 0;
        for (int k = threadIdx.x; k < NBLOCKS; k += NTHREADS) {
            fp += g_pos[k]; fn += g_neg[k]; fc += g_cnt[k];
        }
        #pragma unroll
        for (int o = 16; o > 0; o >>= 1) {
            fp += __shfl_down_sync(0xFFFFFFFFu, fp, o);
            fn += __shfl_down_sync(0xFFFFFFFFu, fn, o);
            fc += __shfl_down_sync(0xFFFFFFFFu, fc, o);
        }
        if (lid == 0) { sp[wid] = fp; sn[wid] = fn; sc[wid] = fc; }
        __syncthreads();
        if (threadIdx.x == 0) {
            constexpr int NW = NTHREADS / 32;
            float bp = 0.0f, bn = 0.0f; int bc = 0;
            #pragma unroll
            for (int w = 0; w < NW; w++) { bp += sp[w]; bn += sn[w]; bc += sc[w]; }
            float n_pos = (float)bc;
            float n_neg = (float)(N_TOTAL - bc);
            out[0] = bp / n_pos + bn / n_neg;
            g_ticket = 0;   // reset for next graph replay
        }
    }
}

extern "C" void kernel_launch(void* const* d_in, const int* in_sizes, int n_in,
                              void* d_out, int out_size) {
    const float4* pred = (const float4*)d_in[0];  // pred_y: float32 [8192,8192]
    const int4*   ty   = (const int4*)  d_in[1];  // true_y: int32   [8192,8192]
    float*        out  = (float*)d_out;

    micro_loss_kernel<<<NBLOCKS, NTHREADS>>>(pred, ty, out);
}

// round 5
// speedup vs baseline: 1.0219x; 1.0219x over previous
#include <cuda_runtime.h>
#include <cuda_bf16.h>

// loss = sum_{pos} softplus(-p)/n_pos + sum_{neg} softplus(p)/n_neg
// over 8192x8192 f32 + i32. Streaming reduction, HBM-bound.
// R5 (= R4 retry after infra failure): 128thr x 1184 blocks (1024 thr/SM ->
// 64-reg budget via launch_bounds) so the 8-deep LDG.128 front-batch fits in
// registers. Compile-time stride -> LDG immediate offsets (no IMAD chain).

#define NBLOCKS  1184        // 148 SMs * 8 CTAs
#define NTHREADS 128
#define N_TOTAL  67108864    // 8192*8192
#define N_VEC4   16777216    // N_TOTAL / 4
#define UNROLL   4
#define STRIDE   (NBLOCKS * NTHREADS)   // 151552, compile-time

__device__ float g_pos[NBLOCKS];
__device__ float g_neg[NBLOCKS];
__device__ int   g_cnt[NBLOCKS];
__device__ int   g_ticket;   // zero-init; last block resets it each launch

// softplus(x)  = log1p(e^{-|x|}) + max(x, 0)
// softplus(-x) = log1p(e^{-|x|}) + max(-x, 0)
// -> one EX2 + one LG2 per element regardless of label.
__device__ __forceinline__ void lane_accum(float x, int y,
                                           float& pos, float& neg, int& cnt) {
    float ax     = fabsf(x);
    float common = __logf(1.0f + __expf(-ax));
    bool  ispos  = (y != 0);
    float relu   = fmaxf(ispos ? -x : x, 0.0f);
    float v      = common + relu;
    pos += ispos ? v : 0.0f;
    neg += ispos ? 0.0f : v;
    cnt += ispos ? 1 : 0;
}

__global__ __launch_bounds__(NTHREADS, 8)   // 8 CTAs/SM -> <=64 regs/thread
void micro_loss_kernel(const float4* __restrict__ pred,
                       const int4*  __restrict__ ty,
                       float* __restrict__ out) {
    float pos = 0.0f, neg = 0.0f;
    int   cnt = 0;

    int i = blockIdx.x * NTHREADS + threadIdx.x;

    // Main loop: ~27 batches of 8 front-issued LDG.128 (offsets are
    // compile-time multiples of STRIDE -> LDG reg+imm addressing).
    for (; i + (UNROLL - 1) * STRIDE < N_VEC4; i += UNROLL * STRIDE) {
        float4 p[UNROLL];
        int4   y[UNROLL];
        #pragma unroll
        for (int k = 0; k < UNROLL; k++) {
            p[k] = __ldcs(pred + i + k * STRIDE);
            y[k] = __ldcs(ty   + i + k * STRIDE);
        }
        #pragma unroll
        for (int k = 0; k < UNROLL; k++) {
            lane_accum(p[k].x, y[k].x, pos, neg, cnt);
            lane_accum(p[k].y, y[k].y, pos, neg, cnt);
            lane_accum(p[k].z, y[k].z, pos, neg, cnt);
            lane_accum(p[k].w, y[k].w, pos, neg, cnt);
        }
    }
    // Remainder (~3 iterations per thread)
    for (; i < N_VEC4; i += STRIDE) {
        float4 p = __ldcs(pred + i);
        int4   y = __ldcs(ty + i);
        lane_accum(p.x, y.x, pos, neg, cnt);
        lane_accum(p.y, y.y, pos, neg, cnt);
        lane_accum(p.z, y.z, pos, neg, cnt);
        lane_accum(p.w, y.w, pos, neg, cnt);
    }

    // Block reduction (fixed tree -> deterministic)
    #pragma unroll
    for (int o = 16; o > 0; o >>= 1) {
        pos += __shfl_down_sync(0xFFFFFFFFu, pos, o);
        neg += __shfl_down_sync(0xFFFFFFFFu, neg, o);
        cnt += __shfl_down_sync(0xFFFFFFFFu, cnt, o);
    }
    __shared__ float sp[NTHREADS / 32];
    __shared__ float sn[NTHREADS / 32];
    __shared__ int   sc[NTHREADS / 32];
    __shared__ bool  s_last;
    int wid = threadIdx.x >> 5;
    int lid = threadIdx.x & 31;
    if (lid == 0) { sp[wid] = pos; sn[wid] = neg; sc[wid] = cnt; }
    __syncthreads();

    if (threadIdx.x == 0) {
        constexpr int NW = NTHREADS / 32;
        float bp = 0.0f, bn = 0.0f; int bc = 0;
        #pragma unroll
        for (int w = 0; w < NW; w++) { bp += sp[w]; bn += sn[w]; bc += sc[w]; }
        g_pos[blockIdx.x] = bp;
        g_neg[blockIdx.x] = bn;
        g_cnt[blockIdx.x] = bc;
        __threadfence();
        int ticket = atomicAdd(&g_ticket, 1);
        s_last = (ticket == NBLOCKS - 1);
    }
    __syncthreads();

    // Last-arriving block does the final reduction (fixed order -> deterministic).
    if (s_last) {
        __threadfence();  // all blocks' partials visible
        float fp = 0.0f, fn = 0.0f; int fc = 0;
        for (int k = threadIdx.x; k < NBLOCKS; k += NTHREADS) {
            fp += g_pos[k]; fn += g_neg[k]; fc += g_cnt[k];
        }
        #pragma unroll
        for (int o = 16; o > 0; o >>= 1) {
            fp += __shfl_down_sync(0xFFFFFFFFu, fp, o);
            fn += __shfl_down_sync(0xFFFFFFFFu, fn, o);
            fc += __shfl_down_sync(0xFFFFFFFFu, fc, o);
        }
        if (lid == 0) { sp[wid] = fp; sn[wid] = fn; sc[wid] = fc; }
        __syncthreads();
        if (threadIdx.x == 0) {
            constexpr int NW = NTHREADS / 32;
            float bp = 0.0f, bn = 0.0f; int bc = 0;
            #pragma unroll
            for (int w = 0; w < NW; w++) { bp += sp[w]; bn += sn[w]; bc += sc[w]; }
            float n_pos = (float)bc;
            float n_neg = (float)(N_TOTAL - bc);
            out[0] = bp / n_pos + bn / n_neg;
            g_ticket = 0;   // reset for next graph replay
        }
    }
}

extern "C" void kernel_launch(void* const* d_in, const int* in_sizes, int n_in,
                              void* d_out, int out_size) {
    const float4* pred = (const float4*)d_in[0];  // pred_y: float32 [8192,8192]
    const int4*   ty   = (const int4*)  d_in[1];  // true_y: int32   [8192,8192]
    float*        out  = (float*)d_out;

    micro_loss_kernel<<<NBLOCKS, NTHREADS>>>(pred, ty, out);
}